// round 1
// baseline (speedup 1.0000x reference)
#include <cuda_runtime.h>
#include <math.h>

// Problem constants
#define NB 8
#define SQ 4096
#define EE 1024
#define HH 16
#define BH (NB*HH)       // 128
#define BS (NB*SQ)       // 32768
#define NCHUNK 32
#define CHUNK 128

// Scratch (static device globals -- allocation-free per harness rules)
__device__ float g_qvec[EE];
__device__ float g_wqk[HH*EE];
__device__ float g_c[HH];
__device__ float g_logits[BH*SQ];
__device__ float g_pm[BH*SQ];
__device__ float g_A[BH*SQ];
__device__ float g_psum[BH];
__device__ float g_partial[NB*NCHUNK*HH*EE];   // 16 MB partial ctx
__device__ float g_ctx[NB*HH*EE];
__device__ float g_hidden[NB*EE];
__device__ float g_hl[NB*EE];
__device__ float g_act[NB*4*EE];

__device__ __forceinline__ float warp_sum(float v){
    #pragma unroll
    for (int o=16;o;o>>=1) v += __shfl_xor_sync(0xffffffffu, v, o);
    return v;
}

// ---------------- K0a: qvec = Wq @ query + bq ----------------
__global__ void __launch_bounds__(256) k_qvec(const float4* __restrict__ Wq4,
                                              const float4* __restrict__ q4,
                                              const float*  __restrict__ bq){
    int lane = threadIdx.x & 31, warp = threadIdx.x >> 5;
    int row = blockIdx.x*8 + warp;
    float acc = 0.f;
    #pragma unroll
    for (int k=0;k<8;k++){
        float4 w = Wq4[row*256 + lane + 32*k];
        float4 q = q4[lane + 32*k];
        acc += w.x*q.x + w.y*q.y + w.z*q.z + w.w*q.w;
    }
    acc = warp_sum(acc);
    if (lane==0) g_qvec[row] = acc + bq[row];
}

// ---------------- K0b: w_qk[h,e] = 0.125 * sum_d q[h,d]*Wk[h*64+d,e]; c[h] ----------------
__global__ void __launch_bounds__(256) k_wqk(const float4* __restrict__ Wk4,
                                             const float*  __restrict__ bk){
    __shared__ float qv[64];
    int h = blockIdx.x, tid = threadIdx.x;
    if (tid < 64) qv[tid] = g_qvec[h*64+tid];
    __syncthreads();
    float4 acc = make_float4(0.f,0.f,0.f,0.f);
    #pragma unroll 8
    for (int d=0; d<64; d++){
        float w = qv[d];
        float4 kk = Wk4[(h*64+d)*256 + tid];
        acc.x += w*kk.x; acc.y += w*kk.y; acc.z += w*kk.z; acc.w += w*kk.w;
    }
    acc.x*=0.125f; acc.y*=0.125f; acc.z*=0.125f; acc.w*=0.125f;
    ((float4*)g_wqk)[h*256+tid] = acc;
    if (tid==0){
        float c=0.f;
        for (int d=0;d<64;d++) c += qv[d]*bk[h*64+d];
        g_c[h] = 0.125f*c;
    }
}

// ---------------- K1: logits[b,h,s] = w_qk[h]·x[b,s] + c[h] (pass 1 over x) ----------------
// 8 warps: (e-half) x (head-quartet). 4 heads/thread, w in regs -> 16 FMA per 16B LDS.
__global__ void __launch_bounds__(256,2) k_logits(const float4* __restrict__ x4){
    __shared__ float4 sx[8*256];     // 8 rows x 1024 floats
    __shared__ float  part[8*32];
    int tid = threadIdx.x, lane = tid&31, warp = tid>>5;
    int eh = warp>>2, hq = warp&3;
    const float4* w4 = (const float4*)g_wqk;
    float4 w[4][4];
    #pragma unroll
    for (int hp=0;hp<4;hp++)
        #pragma unroll
        for (int st=0;st<4;st++)
            w[hp][st] = w4[(hq*4+hp)*256 + eh*128 + st*32 + lane];
    int rowbase = blockIdx.x*32;
    for (int t=0;t<4;t++){
        int rb = rowbase + t*8;
        #pragma unroll
        for (int i=0;i<8;i++) sx[i*256+tid] = x4[(rb+i)*256 + tid];
        __syncthreads();
        float a[32];
        #pragma unroll
        for (int j=0;j<32;j++) a[j]=0.f;
        #pragma unroll
        for (int i=0;i<8;i++){
            #pragma unroll
            for (int st=0;st<4;st++){
                float4 xv = sx[i*256 + eh*128 + st*32 + lane];
                #pragma unroll
                for (int hp=0;hp<4;hp++){
                    a[i*4+hp] += w[hp][st].x*xv.x + w[hp][st].y*xv.y
                               + w[hp][st].z*xv.z + w[hp][st].w*xv.w;
                }
            }
        }
        #pragma unroll
        for (int o=16;o;o>>=1)
            #pragma unroll
            for (int j=0;j<32;j++) a[j] += __shfl_xor_sync(0xffffffffu, a[j], o);
        if (lane==0){
            #pragma unroll
            for (int j=0;j<32;j++) part[warp*32+j] = a[j];
        }
        __syncthreads();
        if (tid<128){
            int i = tid>>4, h = tid&15;
            int hq2 = h>>2, hp = h&3, l = i*4+hp;
            float val = part[hq2*32+l] + part[(4+hq2)*32+l] + g_c[h];
            int r = rb + i, b = r>>12, s = r&4095;
            g_logits[((b<<4)+h)*4096 + s] = val;
        }
        __syncthreads();
    }
}

// ---------------- K2: softmax over S + gumbel hard mask, per (b,h) ----------------
__global__ void __launch_bounds__(256) k_softmax(const float* __restrict__ gu){
    __shared__ float red[8];
    __shared__ float bc;
    int bid = blockIdx.x;                 // b*16+h
    int tid = threadIdx.x, lane = tid&31, warp = tid>>5;
    int base = bid*4096;
    float l[16];
    float m = -1e30f;
    #pragma unroll
    for (int j=0;j<16;j++){ l[j] = g_logits[base + tid + 256*j]; m = fmaxf(m, l[j]); }
    #pragma unroll
    for (int o=16;o;o>>=1) m = fmaxf(m, __shfl_xor_sync(0xffffffffu,m,o));
    if (lane==0) red[warp]=m;
    __syncthreads();
    if (tid==0){ float mm=red[0]; for(int i=1;i<8;i++) mm=fmaxf(mm,red[i]); bc=mm; }
    __syncthreads();
    m = bc;
    float ex[16]; float sum=0.f;
    #pragma unroll
    for (int j=0;j<16;j++){ ex[j]=expf(l[j]-m); sum+=ex[j]; }
    sum = warp_sum(sum);
    if (lane==0) red[warp]=sum;
    __syncthreads();
    if (tid==0){ float ss=0.f; for(int i=0;i<8;i++) ss+=red[i]; bc=ss; }
    __syncthreads();
    float inv = 1.f/bc;
    float ps=0.f;
    #pragma unroll
    for (int j=0;j<16;j++){
        int s = tid+256*j;
        float prob = ex[j]*inv;
        float u0 = gu[(base+s)*2], u1 = gu[(base+s)*2+1];
        float g0 = -logf(-logf(u0+1e-20f)+1e-20f);
        float g1 = -logf(-logf(u1+1e-20f)+1e-20f);
        float A = (l[j]+g1 > g0) ? 1.f : 0.f;
        float pm = A*prob;
        g_A[base+s]=A; g_pm[base+s]=pm; ps+=pm;
    }
    ps = warp_sum(ps);
    if (lane==0) red[warp]=ps;
    __syncthreads();
    if (tid==0){ float ss=0.f; for(int i=0;i<8;i++) ss+=red[i]; g_psum[bid]=ss; }
}

// ---------------- K2b: masks/attn = sum over heads ----------------
__global__ void __launch_bounds__(256) k_sums(float* __restrict__ out){
    int idx = blockIdx.x*256 + threadIdx.x;    // b*4096+s
    int b = idx>>12, s = idx&4095;
    float ms=0.f, as=0.f;
    #pragma unroll
    for (int h=0;h<16;h++){
        int off = ((b<<4)+h)*4096 + s;
        ms += g_A[off];
        as += g_pm[off];
    }
    out[8192+idx] = ms;
    out[8192+32768+idx] = as;
}

// ---------------- K3: ctx partials (pass 2 over x) ----------------
// thread owns 4 e-cols x 16 heads (64 reg accumulators); 64 FMA per 16B global load.
__global__ void __launch_bounds__(256,2) k_ctx(const float4* __restrict__ x4){
    __shared__ float spm[16*128];
    int tid = threadIdx.x;
    int b = blockIdx.x >> 5, chunk = blockIdx.x & 31;
    int s0 = chunk*CHUNK;
    #pragma unroll
    for (int i=0;i<8;i++){
        int idx = tid + 256*i;
        int h = idx>>7, si = idx&127;
        spm[idx] = g_pm[((b<<4)+h)*4096 + s0 + si];
    }
    __syncthreads();
    float4 acc[16];
    #pragma unroll
    for (int h=0;h<16;h++) acc[h] = make_float4(0.f,0.f,0.f,0.f);
    #pragma unroll 4
    for (int si=0; si<CHUNK; si++){
        float4 xv = x4[(b*4096 + s0 + si)*256 + tid];
        #pragma unroll
        for (int h=0;h<16;h++){
            float p = spm[h*128+si];
            acc[h].x += p*xv.x; acc[h].y += p*xv.y;
            acc[h].z += p*xv.z; acc[h].w += p*xv.w;
        }
    }
    float4* p4 = (float4*)g_partial;
    #pragma unroll
    for (int h=0;h<16;h++)
        p4[((b*32+chunk)*16 + h)*256 + tid] = acc[h];
}

// ---------------- K3r: deterministic reduction of ctx partials ----------------
__global__ void __launch_bounds__(256) k_ctxr(){
    int idx = blockIdx.x*256 + threadIdx.x;   // b*16384 + (h*1024+e)
    int b = idx>>14, rem = idx & 16383;
    float s=0.f;
    #pragma unroll
    for (int c=0;c<32;c++) s += g_partial[((b*32+c)<<14) + rem];
    g_ctx[idx] = s;
}

// ---------------- K4a: hidden = Wv·ctx + bv*psum ----------------
__global__ void __launch_bounds__(256) k_hidden(const float4* __restrict__ Wv4,
                                                const float*  __restrict__ bv){
    int lane = threadIdx.x&31, warp = threadIdx.x>>5;
    int row = blockIdx.x*8+warp;
    int h = row>>6;
    float4 w[8];
    #pragma unroll
    for (int k=0;k<8;k++) w[k] = Wv4[row*256 + lane + 32*k];
    const float4* c4 = (const float4*)g_ctx;
    float acc[8];
    #pragma unroll
    for (int b=0;b<8;b++){
        float s=0.f;
        #pragma unroll
        for (int k=0;k<8;k++){
            float4 c = c4[((b<<4)+h)*256 + lane + 32*k];
            s += w[k].x*c.x + w[k].y*c.y + w[k].z*c.z + w[k].w*c.w;
        }
        acc[b]=s;
    }
    #pragma unroll
    for (int o=16;o;o>>=1)
        #pragma unroll
        for (int b=0;b<8;b++) acc[b] += __shfl_xor_sync(0xffffffffu, acc[b], o);
    if (lane==0){
        float bvr = bv[row];
        #pragma unroll
        for (int b=0;b<8;b++) g_hidden[b*1024+row] = acc[b] + bvr*g_psum[(b<<4)+h];
    }
}

// ---------------- K4b: LayerNorm (biased var, eps=1e-5) ----------------
__global__ void __launch_bounds__(256) k_ln(const float* __restrict__ lg,
                                            const float* __restrict__ lb){
    __shared__ float red[8]; __shared__ float bc;
    int b = blockIdx.x, tid = threadIdx.x, lane=tid&31, warp=tid>>5;
    float v[4];
    #pragma unroll
    for (int j=0;j<4;j++) v[j] = g_hidden[b*1024 + tid + 256*j];
    float s = v[0]+v[1]+v[2]+v[3];
    s = warp_sum(s); if (lane==0) red[warp]=s; __syncthreads();
    if (tid==0){ float t=0.f; for(int i=0;i<8;i++)t+=red[i]; bc=t*(1.f/1024.f);} __syncthreads();
    float mu = bc;
    float q=0.f;
    #pragma unroll
    for (int j=0;j<4;j++){ float d=v[j]-mu; q+=d*d; }
    q = warp_sum(q); if(lane==0) red[warp]=q; __syncthreads();
    if (tid==0){ float t=0.f; for(int i=0;i<8;i++)t+=red[i]; bc=rsqrtf(t*(1.f/1024.f)+1e-5f);} __syncthreads();
    float rstd = bc;
    #pragma unroll
    for (int j=0;j<4;j++){
        int i = tid+256*j;
        g_hl[b*1024+i] = (v[j]-mu)*rstd*lg[i] + lb[i];
    }
}

// ---------------- K4c: act = relu(hl @ W1^T + b1) ----------------
__global__ void __launch_bounds__(256) k_mlp1(const float4* __restrict__ W14,
                                              const float*  __restrict__ b1){
    __shared__ float4 hls[2048];   // 8x1024 floats
    int tid = threadIdx.x, lane=tid&31, warp=tid>>5;
    const float4* h4 = (const float4*)g_hl;
    #pragma unroll
    for (int i=0;i<8;i++) hls[tid + 256*i] = h4[tid+256*i];
    __syncthreads();
    int row = blockIdx.x*8+warp;
    float4 w[8];
    #pragma unroll
    for (int k=0;k<8;k++) w[k]=W14[row*256+lane+32*k];
    float acc[8];
    #pragma unroll
    for (int b=0;b<8;b++){
        float s=0.f;
        #pragma unroll
        for (int k=0;k<8;k++){
            float4 hv = hls[b*256 + lane + 32*k];
            s += w[k].x*hv.x + w[k].y*hv.y + w[k].z*hv.z + w[k].w*hv.w;
        }
        acc[b]=s;
    }
    #pragma unroll
    for (int o=16;o;o>>=1)
        #pragma unroll
        for (int b=0;b<8;b++) acc[b] += __shfl_xor_sync(0xffffffffu, acc[b], o);
    if (lane==0){
        float bb = b1[row];
        #pragma unroll
        for (int b=0;b<8;b++) g_act[b*4096+row] = fmaxf(acc[b]+bb, 0.f);
    }
}

// ---------------- K4d: out = act @ W2^T + b2 ----------------
__global__ void __launch_bounds__(256) k_mlp2(const float4* __restrict__ W24,
                                              const float*  __restrict__ b2,
                                              float* __restrict__ out){
    extern __shared__ float4 as4[];    // 8x4096 floats = 128KB dynamic
    int tid=threadIdx.x, lane=tid&31, warp=tid>>5;
    const float4* a4 = (const float4*)g_act;
    #pragma unroll
    for (int i=0;i<32;i++) as4[tid+256*i] = a4[tid+256*i];
    __syncthreads();
    int row = blockIdx.x*8+warp;
    float acc[8];
    #pragma unroll
    for (int b=0;b<8;b++) acc[b]=0.f;
    #pragma unroll 4
    for (int k=0;k<32;k++){
        float4 w = W24[row*1024 + lane + 32*k];
        #pragma unroll
        for (int b=0;b<8;b++){
            float4 av = as4[b*1024 + lane + 32*k];
            acc[b] += w.x*av.x + w.y*av.y + w.z*av.z + w.w*av.w;
        }
    }
    #pragma unroll
    for (int o=16;o;o>>=1)
        #pragma unroll
        for (int b=0;b<8;b++) acc[b] += __shfl_xor_sync(0xffffffffu, acc[b], o);
    if (lane==0){
        float bb = b2[row];
        #pragma unroll
        for (int b=0;b<8;b++) out[b*1024+row] = acc[b] + bb;
    }
}

extern "C" void kernel_launch(void* const* d_in, const int* in_sizes, int n_in,
                              void* d_out, int out_size){
    const float* x     = (const float*)d_in[0];
    const float* gu    = (const float*)d_in[1];
    const float* query = (const float*)d_in[2];
    const float* Wq    = (const float*)d_in[3];
    const float* bq    = (const float*)d_in[4];
    const float* Wk    = (const float*)d_in[5];
    const float* bk    = (const float*)d_in[6];
    const float* Wv    = (const float*)d_in[7];
    const float* bv    = (const float*)d_in[8];
    const float* ln_g  = (const float*)d_in[9];
    const float* ln_b  = (const float*)d_in[10];
    const float* W1    = (const float*)d_in[11];
    const float* b1    = (const float*)d_in[12];
    const float* W2    = (const float*)d_in[13];
    const float* b2    = (const float*)d_in[14];
    float* out = (float*)d_out;

    cudaFuncSetAttribute(k_mlp2, cudaFuncAttributeMaxDynamicSharedMemorySize, 131072);

    k_qvec   <<<128,256>>>((const float4*)Wq, (const float4*)query, bq);
    k_wqk    <<<16,256>>>((const float4*)Wk, bk);
    k_logits <<<1024,256>>>((const float4*)x);
    k_softmax<<<128,256>>>(gu);
    k_sums   <<<128,256>>>(out);
    k_ctx    <<<256,256>>>((const float4*)x);
    k_ctxr   <<<512,256>>>();
    k_hidden <<<128,256>>>((const float4*)Wv, bv);
    k_ln     <<<8,256>>>(ln_g, ln_b);
    k_mlp1   <<<512,256>>>((const float4*)W1, b1);
    k_mlp2   <<<128,256,131072>>>((const float4*)W2, b2, out);
}